// round 2
// baseline (speedup 1.0000x reference)
#include <cuda_runtime.h>
#include <math.h>

#define BATCH 4096
#define FEAT  4096
#define THREADS 256

// Scratch: per-row hinged values + completion ticket (no allocation allowed).
__device__ float        g_row_vals[BATCH];
__device__ unsigned int g_ticket = 0u;

__global__ __launch_bounds__(THREADS)
void fused_loss_kernel(const float* __restrict__ o1,
                       const float* __restrict__ o2,
                       const float* __restrict__ o3,
                       float* __restrict__ out) {
    const int row = blockIdx.x;
    const size_t base = (size_t)row * FEAT;
    const float4* __restrict__ a = reinterpret_cast<const float4*>(o1 + base);
    const float4* __restrict__ b = reinterpret_cast<const float4*>(o2 + base);
    const float4* __restrict__ c = reinterpret_cast<const float4*>(o3 + base);

    const int tid = threadIdx.x;
    const int lane = tid & 31;
    const int wid  = tid >> 5;

    float s13 = 0.0f;
    float s12 = 0.0f;

    // 1024 float4 per row / 256 threads = 4 vec iterations; streaming loads
    // (read-once data, evict-first policy).
#pragma unroll
    for (int it = 0; it < (FEAT / 4) / THREADS; ++it) {
        int i = tid + it * THREADS;
        float4 x = __ldcs(&a[i]);
        float4 y = __ldcs(&b[i]);
        float4 z = __ldcs(&c[i]);

        float d;
        d = x.x - z.x; s13 = fmaf(d, d, s13);
        d = x.y - z.y; s13 = fmaf(d, d, s13);
        d = x.z - z.z; s13 = fmaf(d, d, s13);
        d = x.w - z.w; s13 = fmaf(d, d, s13);

        d = x.x - y.x; s12 = fmaf(d, d, s12);
        d = x.y - y.y; s12 = fmaf(d, d, s12);
        d = x.z - y.z; s12 = fmaf(d, d, s12);
        d = x.w - y.w; s12 = fmaf(d, d, s12);
    }

#pragma unroll
    for (int off = 16; off > 0; off >>= 1) {
        s13 += __shfl_down_sync(0xFFFFFFFFu, s13, off);
        s12 += __shfl_down_sync(0xFFFFFFFFu, s12, off);
    }

    __shared__ float sm13[THREADS / 32];
    __shared__ float sm12[THREADS / 32];
    __shared__ bool  s_is_last;
    if (lane == 0) { sm13[wid] = s13; sm12[wid] = s12; }
    __syncthreads();

    if (tid == 0) {
        float t13 = 0.0f, t12 = 0.0f;
#pragma unroll
        for (int w = 0; w < THREADS / 32; ++w) { t13 += sm13[w]; t12 += sm12[w]; }
        float compare = 2.0f - sqrtf(t13) + sqrtf(t12);
        g_row_vals[row] = fmaxf(0.0f, compare);

        // Make the row value globally visible before taking a ticket.
        __threadfence();
        unsigned int t = atomicAdd(&g_ticket, 1u);
        s_is_last = (t == (unsigned int)(gridDim.x - 1));
    }
    __syncthreads();

    // Last block to finish reduces all row values (fixed order -> deterministic).
    if (s_is_last) {
        float s = 0.0f;
#pragma unroll
        for (int it = 0; it < BATCH / THREADS; ++it)
            s += __ldcg(&g_row_vals[tid + it * THREADS]);

#pragma unroll
        for (int off = 16; off > 0; off >>= 1)
            s += __shfl_down_sync(0xFFFFFFFFu, s, off);

        if (lane == 0) sm13[wid] = s;
        __syncthreads();

        if (tid == 0) {
            float tot = 0.0f;
#pragma unroll
            for (int w = 0; w < THREADS / 32; ++w) tot += sm13[w];
            out[0] = tot * (float)BATCH;   // broadcast-sum over [B,B]
            g_ticket = 0u;                 // reset for next graph replay
        }
    }
}

extern "C" void kernel_launch(void* const* d_in, const int* in_sizes, int n_in,
                              void* d_out, int out_size) {
    const float* o1 = (const float*)d_in[0];
    const float* o2 = (const float*)d_in[1];
    const float* o3 = (const float*)d_in[2];
    float* out = (float*)d_out;

    fused_loss_kernel<<<BATCH, THREADS>>>(o1, o2, o3, out);
}

// round 3
// speedup vs baseline: 1.0771x; 1.0771x over previous
#include <cuda_runtime.h>
#include <math.h>

#define BATCH 4096
#define FEAT  4096
#define THREADS 512

__global__ __launch_bounds__(THREADS)
void fused_loss_kernel(const float* __restrict__ o1,
                       const float* __restrict__ o2,
                       const float* __restrict__ o3,
                       float* __restrict__ out) {
    const int row = blockIdx.x;
    const size_t base = (size_t)row * FEAT;
    const float4* __restrict__ a = reinterpret_cast<const float4*>(o1 + base);
    const float4* __restrict__ b = reinterpret_cast<const float4*>(o2 + base);
    const float4* __restrict__ c = reinterpret_cast<const float4*>(o3 + base);

    const int tid  = threadIdx.x;
    const int lane = tid & 31;
    const int wid  = tid >> 5;

    float s13 = 0.0f;
    float s12 = 0.0f;

    // 1024 float4 per row / 512 threads = 2 vec iterations -> 6 loads in flight
    // per thread (keeps oe*MLP_p1 low to avoid cross-CTA L1tex-queue spread).
#pragma unroll
    for (int it = 0; it < (FEAT / 4) / THREADS; ++it) {
        int i = tid + it * THREADS;
        float4 x = a[i];
        float4 y = b[i];
        float4 z = c[i];

        float d;
        d = x.x - z.x; s13 = fmaf(d, d, s13);
        d = x.y - z.y; s13 = fmaf(d, d, s13);
        d = x.z - z.z; s13 = fmaf(d, d, s13);
        d = x.w - z.w; s13 = fmaf(d, d, s13);

        d = x.x - y.x; s12 = fmaf(d, d, s12);
        d = x.y - y.y; s12 = fmaf(d, d, s12);
        d = x.z - y.z; s12 = fmaf(d, d, s12);
        d = x.w - y.w; s12 = fmaf(d, d, s12);
    }

#pragma unroll
    for (int off = 16; off > 0; off >>= 1) {
        s13 += __shfl_down_sync(0xFFFFFFFFu, s13, off);
        s12 += __shfl_down_sync(0xFFFFFFFFu, s12, off);
    }

    __shared__ float sm13[THREADS / 32];
    __shared__ float sm12[THREADS / 32];
    if (lane == 0) { sm13[wid] = s13; sm12[wid] = s12; }
    __syncthreads();

    if (tid == 0) {
        float t13 = 0.0f, t12 = 0.0f;
#pragma unroll
        for (int w = 0; w < THREADS / 32; ++w) { t13 += sm13[w]; t12 += sm12[w]; }
        float compare = 2.0f - sqrtf(t13) + sqrtf(t12);
        float hinged = fmaxf(0.0f, compare);
        // Broadcast-sum over [B,B] == B * sum_b(hinged). One overlapped ATOMG
        // per block; out[] is zeroed by cudaMemsetAsync in kernel_launch.
        atomicAdd(out, hinged * (float)BATCH);
    }
}

extern "C" void kernel_launch(void* const* d_in, const int* in_sizes, int n_in,
                              void* d_out, int out_size) {
    const float* o1 = (const float*)d_in[0];
    const float* o2 = (const float*)d_in[1];
    const float* o3 = (const float*)d_in[2];
    float* out = (float*)d_out;

    cudaMemsetAsync(out, 0, sizeof(float));
    fused_loss_kernel<<<BATCH, THREADS>>>(o1, o2, o3, out);
}